// round 15
// baseline (speedup 1.0000x reference)
#include <cuda_runtime.h>
#include <cuda_fp16.h>

#define VDIM 128
#define NB   8
#define SLAB 16384
#define VOL  2097152

// Scratch spectrum stored as half2, slab-major: idx = b*VOL + z*SLAB + y*128 + x.
__device__ __half2 g_Z[(size_t)NB * VOL];

__device__ __forceinline__ int brev7(int x) { return (int)(__brev((unsigned)x) >> 25); }
__device__ __forceinline__ int bneg7(int j) {
    int k = brev7(j); k = (VDIM - k) & 127; return brev7(k);
}

__device__ __forceinline__ __half2 pack_h2(float2 v) { return __floats2half2_rn(v.x, v.y); }
__device__ __forceinline__ float2 unpack_h2(__half2 h) { return __half22float2(h); }

// passA/C half2-tile swizzle: 32-bit/32-lane bank-bijective for all phases.
__device__ __forceinline__ int sidxAC(int y, int x) {
    int c = x ^ ((x >> 4) & 7) ^ ((x & 1) << 3)
              ^ (y & 7) ^ ((y >> 4) & 7) ^ ((y & 1) << 3) ^ (y & 8) ^ ((y & 1) << 4);
    return (y << 7) + c;
}
// passB half2-tile swizzle: bank-bijective for vary-sets {l0-3,z0}, {l0-3,z4}, {z0-4}.
__device__ __forceinline__ int sidxB(int l, int z) {
    int c = z ^ ((z >> 3) & 15) ^ (l & 15) ^ ((z & 1) << 4);
    return (l << 7) + c;
}

__device__ __forceinline__ float2 cmul(float2 a, float2 w) {
    return make_float2(a.x * w.x - a.y * w.y, a.x * w.y + a.y * w.x);
}
__device__ __forceinline__ float2 cmulc(float2 a, float2 w) {
    return make_float2(a.x * w.x + a.y * w.y, a.y * w.x - a.x * w.y);
}
__device__ __forceinline__ void bf_fwd(float2& ra, float2& rb, float2 w) {
    float2 a = ra, b = rb;
    ra = make_float2(a.x + b.x, a.y + b.y);
    rb = cmul(make_float2(a.x - b.x, a.y - b.y), w);
}
__device__ __forceinline__ void bf_inv(float2& ra, float2& rb, float2 w) {
    float2 a = ra, t = cmulc(rb, w);
    ra = make_float2(a.x + t.x, a.y + t.y);
    rb = make_float2(a.x - t.x, a.y - t.y);
}
__device__ __forceinline__ void bf_triv_fwd(float2& ra, float2& rb) {
    float2 a = ra, b = rb;
    ra = make_float2(a.x + b.x, a.y + b.y);
    rb = make_float2(a.x - b.x, a.y - b.y);
}

// ===== A'/B' split (passA/passC) =====
__device__ __forceinline__ void fftA2_fwd(float2 r[16], int t, const float2* tw) {
    #pragma unroll
    for (int k = 0; k < 8; ++k)
        bf_fwd(r[k], r[k + 8], tw[16 * (k >> 1) + 2 * t + (k & 1)]);
    #pragma unroll
    for (int g = 0; g < 8; ++g) { int k = ((g & ~3) << 1) | (g & 3);
        bf_fwd(r[k], r[k + 4], tw[32 * ((k >> 1) & 1) + 4 * t + 2 * (k & 1)]); }
    #pragma unroll
    for (int g = 0; g < 8; ++g) { int k = ((g & ~1) << 1) | (g & 1);
        bf_fwd(r[k], r[k + 2], tw[8 * t + 4 * (k & 1)]); }
}
__device__ __forceinline__ void fftA2_inv(float2 r[16], int t, const float2* tw) {
    #pragma unroll
    for (int g = 0; g < 8; ++g) { int k = ((g & ~1) << 1) | (g & 1);
        bf_inv(r[k], r[k + 2], tw[8 * t + 4 * (k & 1)]); }
    #pragma unroll
    for (int g = 0; g < 8; ++g) { int k = ((g & ~3) << 1) | (g & 3);
        bf_inv(r[k], r[k + 4], tw[32 * ((k >> 1) & 1) + 4 * t + 2 * (k & 1)]); }
    #pragma unroll
    for (int k = 0; k < 8; ++k)
        bf_inv(r[k], r[k + 8], tw[16 * (k >> 1) + 2 * t + (k & 1)]);
}
__device__ __forceinline__ void fftB2_fwd(float2 r[16], const float2* tw) {
    #pragma unroll
    for (int m = 0; m < 8; ++m) bf_fwd(r[m], r[m + 8], tw[8 * m]);
    #pragma unroll
    for (int g = 0; g < 8; ++g) { int m = ((g & ~3) << 1) | (g & 3);
        bf_fwd(r[m], r[m + 4], tw[16 * (m & 3)]); }
    #pragma unroll
    for (int g = 0; g < 8; ++g) { int m = ((g & ~1) << 1) | (g & 1);
        bf_fwd(r[m], r[m + 2], tw[32 * (m & 1)]); }
    #pragma unroll
    for (int g = 0; g < 8; ++g) bf_triv_fwd(r[2 * g], r[2 * g + 1]);
}
__device__ __forceinline__ void fftB2_inv(float2 r[16], const float2* tw) {
    #pragma unroll
    for (int g = 0; g < 8; ++g) bf_triv_fwd(r[2 * g], r[2 * g + 1]);
    #pragma unroll
    for (int g = 0; g < 8; ++g) { int m = ((g & ~1) << 1) | (g & 1);
        bf_inv(r[m], r[m + 2], tw[32 * (m & 1)]); }
    #pragma unroll
    for (int g = 0; g < 8; ++g) { int m = ((g & ~3) << 1) | (g & 3);
        bf_inv(r[m], r[m + 4], tw[16 * (m & 3)]); }
    #pragma unroll
    for (int m = 0; m < 8; ++m) bf_inv(r[m], r[m + 8], tw[8 * m]);
}

// ===== old A/B split (passB) =====
__device__ __forceinline__ void fftA_fwd(float2 r[16], int t, const float2* tw,
                                         const float2* tw4, const float2* tw8) {
    #pragma unroll
    for (int j = 0; j < 8; ++j) bf_fwd(r[j], r[j + 8], tw[t + 8 * j]);
    #pragma unroll
    for (int g = 0; g < 8; ++g) { int j = ((g & ~3) << 1) | (g & 3); bf_fwd(r[j], r[j + 4], tw[2 * (t + 8 * (j & 3))]); }
    #pragma unroll
    for (int g = 0; g < 8; ++g) { int j = ((g & ~1) << 1) | (g & 1); bf_fwd(r[j], r[j + 2], tw4[t + 8 * (j & 1)]); }
    #pragma unroll
    for (int g = 0; g < 8; ++g) { int j = 2 * g; bf_fwd(r[j], r[j + 1], tw8[t]); }
}
__device__ __forceinline__ void fftA_inv(float2 r[16], int t, const float2* tw,
                                         const float2* tw4, const float2* tw8) {
    #pragma unroll
    for (int g = 0; g < 8; ++g) { int j = 2 * g; bf_inv(r[j], r[j + 1], tw8[t]); }
    #pragma unroll
    for (int g = 0; g < 8; ++g) { int j = ((g & ~1) << 1) | (g & 1); bf_inv(r[j], r[j + 2], tw4[t + 8 * (j & 1)]); }
    #pragma unroll
    for (int g = 0; g < 8; ++g) { int j = ((g & ~3) << 1) | (g & 3); bf_inv(r[j], r[j + 4], tw[2 * (t + 8 * (j & 3))]); }
    #pragma unroll
    for (int j = 0; j < 8; ++j) bf_inv(r[j], r[j + 8], tw[t + 8 * j]);
}
__device__ __forceinline__ void fftB_fwd(float2 r[16], const float2* tw) {
    #pragma unroll
    for (int g = 0; g < 8; ++g) { int m = ((g & ~3) << 1) | (g & 3); bf_fwd(r[m], r[m + 4], tw[(m & 3) << 4]); }
    #pragma unroll
    for (int g = 0; g < 8; ++g) { int m = ((g & ~1) << 1) | (g & 1); bf_fwd(r[m], r[m + 2], tw[(m & 1) << 5]); }
    #pragma unroll
    for (int g = 0; g < 8; ++g) bf_triv_fwd(r[2 * g], r[2 * g + 1]);
}
__device__ __forceinline__ void fftB_inv(float2 r[16], const float2* tw) {
    #pragma unroll
    for (int g = 0; g < 8; ++g) bf_triv_fwd(r[2 * g], r[2 * g + 1]);
    #pragma unroll
    for (int g = 0; g < 8; ++g) { int m = ((g & ~1) << 1) | (g & 1); bf_inv(r[m], r[m + 2], tw[(m & 1) << 5]); }
    #pragma unroll
    for (int g = 0; g < 8; ++g) { int m = ((g & ~3) << 1) | (g & 3); bf_inv(r[m], r[m + 4], tw[(m & 3) << 4]); }
}
__device__ __forceinline__ void init_tw1(float2* tw, int nthr) {
    for (int i = threadIdx.x; i < 64; i += nthr) {
        float sn, cs; sincospif(i * (1.0f / 64.0f), &sn, &cs);
        tw[i] = make_float2(cs, -sn);
    }
}
__device__ __forceinline__ void init_tw3(float2* tw, float2* tw4, float2* tw8, int nthr) {
    for (int i = threadIdx.x; i < 64; i += nthr) {
        float sn, cs; sincospif(i * (1.0f / 64.0f), &sn, &cs);
        float2 w = make_float2(cs, -sn);
        tw[i] = w;
        if (!(i & 3)) tw4[i >> 2] = w;
        if (!(i & 7)) tw8[i >> 3] = w;
    }
}

// Pass A: pack v1 + i*v2, forward FFT along x then y per (b,z) slab.
__global__ __launch_bounds__(256, 2) void passA(const float* __restrict__ v1,
                                                const float* __restrict__ v2) {
    extern __shared__ char raw[];
    __half2* tile = (__half2*)raw;                     // 128*128 half2 = 65,536 B
    float2* tw = (float2*)(raw + 65536);
    init_tw1(tw, 256);
    const int tid = threadIdx.x, w2 = tid >> 5, lane = tid & 31;
    const int t = lane & 7, q = (lane >> 3) & 1, h = lane >> 4;
    const size_t base = (size_t)blockIdx.x * SLAB;
    float2 r[16];
    __syncthreads();
    #pragma unroll 1
    for (int it = 0; it < 4; ++it) {                   // x-dim, pattern A' (float2 gmem in)
        const int y = 2 * w2 + 32 * (it >> 1) + 16 * q + h + 64 * (it & 1);
        const float* p1 = v1 + base + y * VDIM + 2 * t;
        const float* p2 = v2 + base + y * VDIM + 2 * t;
        #pragma unroll
        for (int j = 0; j < 8; ++j) {
            const float2 a = *(const float2*)(p1 + 16 * j);
            const float2 b = *(const float2*)(p2 + 16 * j);
            r[2 * j]     = make_float2(a.x, b.x);
            r[2 * j + 1] = make_float2(a.y, b.y);
        }
        fftA2_fwd(r, t, tw);
        #pragma unroll
        for (int k = 0; k < 16; ++k)
            tile[sidxAC(y, 16 * (k >> 1) + 2 * t + (k & 1))] = pack_h2(r[k]);
    }
    __syncwarp();
    #pragma unroll 1
    for (int it = 0; it < 4; ++it) {                   // x-dim, pattern B'
        const int y = 2 * w2 + 32 * (it >> 1) + q + 16 * h + 64 * (it & 1);
        #pragma unroll
        for (int m = 0; m < 16; ++m) r[m] = unpack_h2(tile[sidxAC(y, 16 * t + m)]);
        fftB2_fwd(r, tw);
        #pragma unroll
        for (int m = 0; m < 16; ++m) tile[sidxAC(y, 16 * t + m)] = pack_h2(r[m]);
    }
    __syncthreads();
    #pragma unroll 1
    for (int it = 0; it < 4; ++it) {                   // y-dim, pattern A'
        const int x = 2 * w2 + 32 * (it >> 1) + 16 * q + h + 64 * (it & 1);
        #pragma unroll
        for (int k = 0; k < 16; ++k)
            r[k] = unpack_h2(tile[sidxAC(16 * (k >> 1) + 2 * t + (k & 1), x)]);
        fftA2_fwd(r, t, tw);
        #pragma unroll
        for (int k = 0; k < 16; ++k)
            tile[sidxAC(16 * (k >> 1) + 2 * t + (k & 1), x)] = pack_h2(r[k]);
    }
    __syncthreads();
    #pragma unroll 1
    for (int it = 0; it < 4; ++it) {                   // y-dim, pattern B' (coalesced g_Z out)
        const int x = lane + 32 * (it >> 1) + 64 * (it & 1);
        #pragma unroll
        for (int m = 0; m < 16; ++m) r[m] = unpack_h2(tile[sidxAC(16 * w2 + m, x)]);
        fftB2_fwd(r, tw);
        #pragma unroll
        for (int m = 0; m < 16; ++m)
            g_Z[base + (size_t)(16 * w2 + m) * VDIM + x] = pack_h2(r[m]);
    }
}

// Pointwise with folded 1/N^3 normalization: keeps fp16 tile values ~O(1).
__device__ __forceinline__ float2 Hval(float2 Z, float2 Zn) {
    const float QS = 0.25f / (float)VOL;
    const float px = Z.x + Zn.x, py = Z.y - Zn.y;   // 2*F1
    const float qx = Z.x - Zn.x, qy = Z.y + Zn.y;   // 2i*F2
    return make_float2(QS * (px * qy - py * qx),
                       QS * (px * qx + py * qy));
}

// Pass B: z-FFT + pointwise (normalized) + inverse z-FFT; half2 tile, 2 CTAs/SM.
__global__ __launch_bounds__(256, 2) void passB() {
    extern __shared__ char raw[];
    __half2* tile = (__half2*)raw;                  // 64 lines x 128 (z) half2 = 32,768 B
    float2* tw = (float2*)(raw + 32768);
    float2* tw4 = tw + 64; float2* tw8 = tw4 + 16;
    const int xt = blockIdx.x, jy = blockIdx.y, b = blockIdx.z;
    const int jy2 = bneg7(jy);
    const int xt2 = (xt < 2) ? xt : (5 - xt);
    if (jy2 < jy || (jy2 == jy && xt2 < xt)) return;
    const bool full = (jy2 == jy);
    init_tw3(tw, tw4, tw8, 256);
    const int tid = threadIdx.x;
    const int t = (tid >> 4) & 7;
    const int l0 = ((tid >> 7) << 4) | (tid & 15);
    const int l1 = l0 + 32;
    const size_t vb = (size_t)b * VOL;
    const size_t gb0 = vb + (size_t)jy  * VDIM + (32 * xt  + l0);
    const size_t gb1 = vb + (size_t)jy2 * VDIM + (32 * xt2 + l0);
    float2 r[16];
    __syncthreads();
    #pragma unroll
    for (int j = 0; j < 16; ++j) r[j] = unpack_h2(g_Z[gb0 + (size_t)(t + 8 * j) * SLAB]);
    fftA_fwd(r, t, tw, tw4, tw8);
    #pragma unroll
    for (int j = 0; j < 16; ++j) tile[sidxB(l0, t + 8 * j)] = pack_h2(r[j]);
    #pragma unroll
    for (int j = 0; j < 16; ++j) r[j] = unpack_h2(g_Z[gb1 + (size_t)(t + 8 * j) * SLAB]);
    fftA_fwd(r, t, tw, tw4, tw8);
    #pragma unroll
    for (int j = 0; j < 16; ++j) tile[sidxB(l1, t + 8 * j)] = pack_h2(r[j]);
    __syncthreads();
    #pragma unroll
    for (int m = 0; m < 16; ++m) r[m] = unpack_h2(tile[sidxB(l0, 16 * t + m)]);
    fftB_fwd(r, tw);
    #pragma unroll
    for (int m = 0; m < 16; ++m) tile[sidxB(l0, 16 * t + m)] = pack_h2(r[m]);
    #pragma unroll
    for (int m = 0; m < 16; ++m) r[m] = unpack_h2(tile[sidxB(l1, 16 * t + m)]);
    fftB_fwd(r, tw);
    #pragma unroll
    for (int m = 0; m < 16; ++m) tile[sidxB(l1, 16 * t + m)] = pack_h2(r[m]);
    __syncthreads();
    #pragma unroll 1
    for (int i = tid; i < 32 * 128; i += 256) {
        const int jz = i & 127, row = i >> 7;
        const int jzn = bneg7(jz);
        if (jzn < jz) continue;
        const int pr = 32 + bneg7(32 * xt + row) - 32 * xt2;
        const float2 a1 = unpack_h2(tile[sidxB(row, jz)]);
        const float2 a2 = unpack_h2(tile[sidxB(row, jzn)]);
        const float2 b1 = unpack_h2(tile[sidxB(pr, jz)]);
        const float2 b2 = unpack_h2(tile[sidxB(pr, jzn)]);
        tile[sidxB(row, jz)]  = pack_h2(Hval(a1, b2));
        tile[sidxB(pr, jz)]   = pack_h2(Hval(b1, a2));
        tile[sidxB(row, jzn)] = pack_h2(Hval(a2, b1));
        tile[sidxB(pr, jzn)]  = pack_h2(Hval(b2, a1));
    }
    __syncthreads();
    #pragma unroll
    for (int m = 0; m < 16; ++m) r[m] = unpack_h2(tile[sidxB(l0, 16 * t + m)]);
    fftB_inv(r, tw);
    #pragma unroll
    for (int m = 0; m < 16; ++m) tile[sidxB(l0, 16 * t + m)] = pack_h2(r[m]);
    if (full) {
        #pragma unroll
        for (int m = 0; m < 16; ++m) r[m] = unpack_h2(tile[sidxB(l1, 16 * t + m)]);
        fftB_inv(r, tw);
        #pragma unroll
        for (int m = 0; m < 16; ++m) tile[sidxB(l1, 16 * t + m)] = pack_h2(r[m]);
    }
    __syncthreads();
    #pragma unroll
    for (int j = 0; j < 16; ++j) r[j] = unpack_h2(tile[sidxB(l0, t + 8 * j)]);
    fftA_inv(r, t, tw, tw4, tw8);
    #pragma unroll
    for (int j = 0; j < 16; ++j)
        g_Z[gb0 + (size_t)(t + 8 * j) * SLAB] = pack_h2(r[j]);
    if (full) {
        #pragma unroll
        for (int j = 0; j < 16; ++j) r[j] = unpack_h2(tile[sidxB(l1, t + 8 * j)]);
        fftA_inv(r, t, tw, tw4, tw8);
        #pragma unroll
        for (int j = 0; j < 16; ++j)
            g_Z[gb1 + (size_t)(t + 8 * j) * SLAB] = pack_h2(r[j]);
    }
}

// Pass C: gather half-spectrum + mirror conj fill, inverse y then x FFTs, float2 out.
__global__ __launch_bounds__(256, 2) void passC(float* __restrict__ out) {
    extern __shared__ char raw[];
    __half2* tile = (__half2*)raw;
    float2* tw = (float2*)(raw + 65536);
    init_tw1(tw, 256);
    const int tid = threadIdx.x, w2 = tid >> 5, lane = tid & 31;
    const int t = lane & 7, q = (lane >> 3) & 1, h = lane >> 4;
    const size_t base = (size_t)blockIdx.x * SLAB;
    float2 r[16];
    __syncthreads();
    // gather copy-in: load kept rows (jy <= bneg7(jy)); mirror-fill conj rows.
    #pragma unroll 1
    for (int jy = w2; jy < 128; jy += 8) {
        const int jy2 = bneg7(jy);
        if (jy > jy2) continue;
        #pragma unroll
        for (int k = 0; k < 4; ++k) {
            const int xx = lane + 32 * k;
            __half2 v = g_Z[base + (size_t)jy * VDIM + xx];
            tile[sidxAC(jy, xx)] = v;
            if (jy2 != jy) {
                __half2 c = v; c.y = __hneg(c.y);
                tile[sidxAC(jy2, bneg7(xx))] = c;
            }
        }
    }
    __syncthreads();
    #pragma unroll 1
    for (int it = 0; it < 4; ++it) {                   // y-dim, pattern B' (from smem)
        const int x = lane + 32 * (it >> 1) + 64 * (it & 1);
        #pragma unroll
        for (int m = 0; m < 16; ++m) r[m] = unpack_h2(tile[sidxAC(16 * w2 + m, x)]);
        fftB2_inv(r, tw);
        #pragma unroll
        for (int m = 0; m < 16; ++m) tile[sidxAC(16 * w2 + m, x)] = pack_h2(r[m]);
    }
    __syncthreads();
    #pragma unroll 1
    for (int it = 0; it < 4; ++it) {                   // y-dim, pattern A'
        const int x = 2 * w2 + 32 * (it >> 1) + 16 * q + h + 64 * (it & 1);
        #pragma unroll
        for (int k = 0; k < 16; ++k)
            r[k] = unpack_h2(tile[sidxAC(16 * (k >> 1) + 2 * t + (k & 1), x)]);
        fftA2_inv(r, t, tw);
        #pragma unroll
        for (int k = 0; k < 16; ++k)
            tile[sidxAC(16 * (k >> 1) + 2 * t + (k & 1), x)] = pack_h2(r[k]);
    }
    __syncthreads();
    #pragma unroll 1
    for (int it = 0; it < 4; ++it) {                   // x-dim, pattern B'
        const int y = 2 * w2 + 32 * (it >> 1) + q + 16 * h + 64 * (it & 1);
        #pragma unroll
        for (int m = 0; m < 16; ++m) r[m] = unpack_h2(tile[sidxAC(y, 16 * t + m)]);
        fftB2_inv(r, tw);
        #pragma unroll
        for (int m = 0; m < 16; ++m) tile[sidxAC(y, 16 * t + m)] = pack_h2(r[m]);
    }
    __syncwarp();
    #pragma unroll 1
    for (int it = 0; it < 4; ++it) {                   // x-dim, pattern A' -> float2 out
        const int y = 2 * w2 + 32 * (it >> 1) + 16 * q + h + 64 * (it & 1);
        #pragma unroll
        for (int k = 0; k < 16; ++k)
            r[k] = unpack_h2(tile[sidxAC(y, 16 * (k >> 1) + 2 * t + (k & 1))]);
        fftA2_inv(r, t, tw);
        float* po = out + base + y * VDIM + 2 * t;
        #pragma unroll
        for (int j = 0; j < 8; ++j)
            *(float2*)(po + 16 * j) = make_float2(r[2 * j].x, r[2 * j + 1].x);
    }
}

extern "C" void kernel_launch(void* const* d_in, const int* in_sizes, int n_in,
                              void* d_out, int out_size) {
    const float* v1 = (const float*)d_in[0];
    const float* v2 = (const float*)d_in[1];
    float* out = (float*)d_out;
    const int smAC = 65536 + 64 * (int)sizeof(float2);   // 66,048 B
    const int smB  = 32768 + 88 * (int)sizeof(float2);   // 33,472 B
    cudaFuncSetAttribute(passA, cudaFuncAttributeMaxDynamicSharedMemorySize, smAC);
    cudaFuncSetAttribute(passC, cudaFuncAttributeMaxDynamicSharedMemorySize, smAC);
    cudaFuncSetAttribute(passB, cudaFuncAttributeMaxDynamicSharedMemorySize, smB);
    passA<<<NB * VDIM, 256, smAC>>>(v1, v2);
    passB<<<dim3(4, VDIM, NB), 256, smB>>>();
    passC<<<NB * VDIM, 256, smAC>>>(out);
}

// round 16
// speedup vs baseline: 1.0793x; 1.0793x over previous
#include <cuda_runtime.h>
#include <cuda_fp16.h>

#define VDIM 128
#define NB   8
#define SLAB 16384
#define VOL  2097152

// Scratch spectrum stored as half2, slab-major: idx = b*VOL + z*SLAB + y*128 + x.
__device__ __half2 g_Z[(size_t)NB * VOL];

__device__ __forceinline__ int brev7(int x) { return (int)(__brev((unsigned)x) >> 25); }
__device__ __forceinline__ int bneg7(int j) {
    int k = brev7(j); k = (VDIM - k) & 127; return brev7(k);
}

__device__ __forceinline__ __half2 pack_h2(float2 v) { return __floats2half2_rn(v.x, v.y); }
__device__ __forceinline__ float2 unpack_h2(__half2 h) { return __half22float2(h); }

// passA/C half2-tile swizzle: 32-bit/32-lane bank-bijective for all phases.
__device__ __forceinline__ int sidxAC(int y, int x) {
    int c = x ^ ((x >> 4) & 7) ^ ((x & 1) << 3)
              ^ (y & 7) ^ ((y >> 4) & 7) ^ ((y & 1) << 3) ^ (y & 8) ^ ((y & 1) << 4);
    return (y << 7) + c;
}
// passB fp32-tile swizzle (64-bit criterion, proven in earlier rounds).
__device__ __forceinline__ int sidxB(int l, int z) {
    int c = z ^ ((z >> 4) & 7) ^ (l & 15);
    return (l << 7) + c;
}

// Twiddle constants for specialized stages.
#define C8F 0.92387953251128674f
#define S8F 0.38268343236508978f
#define C4F 0.70710678118654752f

__device__ __forceinline__ float2 cmul(float2 a, float2 w) {
    return make_float2(a.x * w.x - a.y * w.y, a.x * w.y + a.y * w.x);
}
__device__ __forceinline__ float2 cmulc(float2 a, float2 w) {
    return make_float2(a.x * w.x + a.y * w.y, a.y * w.x - a.x * w.y);
}
__device__ __forceinline__ void bf_fwd(float2& ra, float2& rb, float2 w) {
    float2 a = ra, b = rb;
    ra = make_float2(a.x + b.x, a.y + b.y);
    rb = cmul(make_float2(a.x - b.x, a.y - b.y), w);
}
__device__ __forceinline__ void bf_inv(float2& ra, float2& rb, float2 w) {
    float2 a = ra, t = cmulc(rb, w);
    ra = make_float2(a.x + t.x, a.y + t.y);
    rb = make_float2(a.x - t.x, a.y - t.y);
}
__device__ __forceinline__ void bf_triv_fwd(float2& ra, float2& rb) {
    float2 a = ra, b = rb;
    ra = make_float2(a.x + b.x, a.y + b.y);
    rb = make_float2(a.x - b.x, a.y - b.y);
}
// w given as immediate constants
__device__ __forceinline__ void bf_fwd_c(float2& ra, float2& rb, float wx, float wy) {
    float2 a = ra, b = rb;
    ra = make_float2(a.x + b.x, a.y + b.y);
    float dx = a.x - b.x, dy = a.y - b.y;
    rb = make_float2(dx * wx - dy * wy, dx * wy + dy * wx);
}
__device__ __forceinline__ void bf_inv_c(float2& ra, float2& rb, float wx, float wy) {
    float2 a = ra;
    float tx = rb.x * wx + rb.y * wy, ty = rb.y * wx - rb.x * wy;
    ra = make_float2(a.x + tx, a.y + ty);
    rb = make_float2(a.x - tx, a.y - ty);
}
// w = -i : cmul(d,(0,-1)) = (d.y, -d.x)
__device__ __forceinline__ void bf_fwd_mi(float2& ra, float2& rb) {
    float2 a = ra, b = rb;
    ra = make_float2(a.x + b.x, a.y + b.y);
    rb = make_float2(a.y - b.y, b.x - a.x);
}
// t = b * conj(-i) = b * i = (-b.y, b.x)
__device__ __forceinline__ void bf_inv_mi(float2& ra, float2& rb) {
    float2 a = ra;
    float tx = -rb.y, ty = rb.x;
    ra = make_float2(a.x + tx, a.y + ty);
    rb = make_float2(a.x - tx, a.y - ty);
}

// ===== A'/B' split (passA/passC) =====
__device__ __forceinline__ void fftA2_fwd(float2 r[16], int t, const float2* tw) {
    #pragma unroll
    for (int k = 0; k < 8; ++k)
        bf_fwd(r[k], r[k + 8], tw[16 * (k >> 1) + 2 * t + (k & 1)]);
    #pragma unroll
    for (int g = 0; g < 8; ++g) { int k = ((g & ~3) << 1) | (g & 3);
        bf_fwd(r[k], r[k + 4], tw[32 * ((k >> 1) & 1) + 4 * t + 2 * (k & 1)]); }
    #pragma unroll
    for (int g = 0; g < 8; ++g) { int k = ((g & ~1) << 1) | (g & 1);
        bf_fwd(r[k], r[k + 2], tw[8 * t + 4 * (k & 1)]); }
}
__device__ __forceinline__ void fftA2_inv(float2 r[16], int t, const float2* tw) {
    #pragma unroll
    for (int g = 0; g < 8; ++g) { int k = ((g & ~1) << 1) | (g & 1);
        bf_inv(r[k], r[k + 2], tw[8 * t + 4 * (k & 1)]); }
    #pragma unroll
    for (int g = 0; g < 8; ++g) { int k = ((g & ~3) << 1) | (g & 3);
        bf_inv(r[k], r[k + 4], tw[32 * ((k >> 1) & 1) + 4 * t + 2 * (k & 1)]); }
    #pragma unroll
    for (int k = 0; k < 8; ++k)
        bf_inv(r[k], r[k + 8], tw[16 * (k >> 1) + 2 * t + (k & 1)]);
}
// B' stages (8,4,2,1) with compile-time twiddles.
__device__ __forceinline__ void fftB2_fwd(float2 r[16]) {
    // half=8: w = exp(-i*pi*m/8)
    bf_triv_fwd(r[0], r[8]);
    bf_fwd_c(r[1], r[9],  C8F, -S8F);
    bf_fwd_c(r[2], r[10], C4F, -C4F);
    bf_fwd_c(r[3], r[11], S8F, -C8F);
    bf_fwd_mi(r[4], r[12]);
    bf_fwd_c(r[5], r[13], -S8F, -C8F);
    bf_fwd_c(r[6], r[14], -C4F, -C4F);
    bf_fwd_c(r[7], r[15], -C8F, -S8F);
    // half=4: pairs (m, m+4), m in {0,1,2,3, 8,9,10,11}, w = exp(-i*pi*(m&3)/4)
    bf_triv_fwd(r[0], r[4]);  bf_fwd_c(r[1], r[5],  C4F, -C4F);
    bf_fwd_mi(r[2], r[6]);    bf_fwd_c(r[3], r[7],  -C4F, -C4F);
    bf_triv_fwd(r[8], r[12]); bf_fwd_c(r[9], r[13], C4F, -C4F);
    bf_fwd_mi(r[10], r[14]);  bf_fwd_c(r[11], r[15], -C4F, -C4F);
    // half=2: pairs (m, m+2), m in {0,1,4,5,8,9,12,13}, w = 1 or -i
    bf_triv_fwd(r[0], r[2]);   bf_fwd_mi(r[1], r[3]);
    bf_triv_fwd(r[4], r[6]);   bf_fwd_mi(r[5], r[7]);
    bf_triv_fwd(r[8], r[10]);  bf_fwd_mi(r[9], r[11]);
    bf_triv_fwd(r[12], r[14]); bf_fwd_mi(r[13], r[15]);
    // half=1: trivial
    #pragma unroll
    for (int g = 0; g < 8; ++g) bf_triv_fwd(r[2 * g], r[2 * g + 1]);
}
__device__ __forceinline__ void fftB2_inv(float2 r[16]) {
    #pragma unroll
    for (int g = 0; g < 8; ++g) bf_triv_fwd(r[2 * g], r[2 * g + 1]);
    bf_triv_fwd(r[0], r[2]);   bf_inv_mi(r[1], r[3]);
    bf_triv_fwd(r[4], r[6]);   bf_inv_mi(r[5], r[7]);
    bf_triv_fwd(r[8], r[10]);  bf_inv_mi(r[9], r[11]);
    bf_triv_fwd(r[12], r[14]); bf_inv_mi(r[13], r[15]);
    bf_triv_fwd(r[0], r[4]);  bf_inv_c(r[1], r[5],  C4F, -C4F);
    bf_inv_mi(r[2], r[6]);    bf_inv_c(r[3], r[7],  -C4F, -C4F);
    bf_triv_fwd(r[8], r[12]); bf_inv_c(r[9], r[13], C4F, -C4F);
    bf_inv_mi(r[10], r[14]);  bf_inv_c(r[11], r[15], -C4F, -C4F);
    bf_triv_fwd(r[0], r[8]);
    bf_inv_c(r[1], r[9],  C8F, -S8F);
    bf_inv_c(r[2], r[10], C4F, -C4F);
    bf_inv_c(r[3], r[11], S8F, -C8F);
    bf_inv_mi(r[4], r[12]);
    bf_inv_c(r[5], r[13], -S8F, -C8F);
    bf_inv_c(r[6], r[14], -C4F, -C4F);
    bf_inv_c(r[7], r[15], -C8F, -S8F);
}

// ===== old A/B split (passB) =====
__device__ __forceinline__ void fftA_fwd(float2 r[16], int t, const float2* tw,
                                         const float2* tw4, const float2* tw8) {
    #pragma unroll
    for (int j = 0; j < 8; ++j) bf_fwd(r[j], r[j + 8], tw[t + 8 * j]);
    #pragma unroll
    for (int g = 0; g < 8; ++g) { int j = ((g & ~3) << 1) | (g & 3); bf_fwd(r[j], r[j + 4], tw[2 * (t + 8 * (j & 3))]); }
    #pragma unroll
    for (int g = 0; g < 8; ++g) { int j = ((g & ~1) << 1) | (g & 1); bf_fwd(r[j], r[j + 2], tw4[t + 8 * (j & 1)]); }
    #pragma unroll
    for (int g = 0; g < 8; ++g) { int j = 2 * g; bf_fwd(r[j], r[j + 1], tw8[t]); }
}
__device__ __forceinline__ void fftA_inv(float2 r[16], int t, const float2* tw,
                                         const float2* tw4, const float2* tw8) {
    #pragma unroll
    for (int g = 0; g < 8; ++g) { int j = 2 * g; bf_inv(r[j], r[j + 1], tw8[t]); }
    #pragma unroll
    for (int g = 0; g < 8; ++g) { int j = ((g & ~1) << 1) | (g & 1); bf_inv(r[j], r[j + 2], tw4[t + 8 * (j & 1)]); }
    #pragma unroll
    for (int g = 0; g < 8; ++g) { int j = ((g & ~3) << 1) | (g & 3); bf_inv(r[j], r[j + 4], tw[2 * (t + 8 * (j & 3))]); }
    #pragma unroll
    for (int j = 0; j < 8; ++j) bf_inv(r[j], r[j + 8], tw[t + 8 * j]);
}
// B stages (4,2,1) with compile-time twiddles.
__device__ __forceinline__ void fftB_fwd(float2 r[16]) {
    bf_triv_fwd(r[0], r[4]);  bf_fwd_c(r[1], r[5],  C4F, -C4F);
    bf_fwd_mi(r[2], r[6]);    bf_fwd_c(r[3], r[7],  -C4F, -C4F);
    bf_triv_fwd(r[8], r[12]); bf_fwd_c(r[9], r[13], C4F, -C4F);
    bf_fwd_mi(r[10], r[14]);  bf_fwd_c(r[11], r[15], -C4F, -C4F);
    bf_triv_fwd(r[0], r[2]);   bf_fwd_mi(r[1], r[3]);
    bf_triv_fwd(r[4], r[6]);   bf_fwd_mi(r[5], r[7]);
    bf_triv_fwd(r[8], r[10]);  bf_fwd_mi(r[9], r[11]);
    bf_triv_fwd(r[12], r[14]); bf_fwd_mi(r[13], r[15]);
    #pragma unroll
    for (int g = 0; g < 8; ++g) bf_triv_fwd(r[2 * g], r[2 * g + 1]);
}
__device__ __forceinline__ void fftB_inv(float2 r[16]) {
    #pragma unroll
    for (int g = 0; g < 8; ++g) bf_triv_fwd(r[2 * g], r[2 * g + 1]);
    bf_triv_fwd(r[0], r[2]);   bf_inv_mi(r[1], r[3]);
    bf_triv_fwd(r[4], r[6]);   bf_inv_mi(r[5], r[7]);
    bf_triv_fwd(r[8], r[10]);  bf_inv_mi(r[9], r[11]);
    bf_triv_fwd(r[12], r[14]); bf_inv_mi(r[13], r[15]);
    bf_triv_fwd(r[0], r[4]);  bf_inv_c(r[1], r[5],  C4F, -C4F);
    bf_inv_mi(r[2], r[6]);    bf_inv_c(r[3], r[7],  -C4F, -C4F);
    bf_triv_fwd(r[8], r[12]); bf_inv_c(r[9], r[13], C4F, -C4F);
    bf_inv_mi(r[10], r[14]);  bf_inv_c(r[11], r[15], -C4F, -C4F);
}
__device__ __forceinline__ void init_tw1(float2* tw, int nthr) {
    for (int i = threadIdx.x; i < 64; i += nthr) {
        float sn, cs; sincospif(i * (1.0f / 64.0f), &sn, &cs);
        tw[i] = make_float2(cs, -sn);
    }
}
__device__ __forceinline__ void init_tw3(float2* tw, float2* tw4, float2* tw8, int nthr) {
    for (int i = threadIdx.x; i < 64; i += nthr) {
        float sn, cs; sincospif(i * (1.0f / 64.0f), &sn, &cs);
        float2 w = make_float2(cs, -sn);
        tw[i] = w;
        if (!(i & 3)) tw4[i >> 2] = w;
        if (!(i & 7)) tw8[i >> 3] = w;
    }
}

// Pass A: pack v1 + i*v2, forward FFT along x then y per (b,z) slab.
__global__ __launch_bounds__(256, 2) void passA(const float* __restrict__ v1,
                                                const float* __restrict__ v2) {
    extern __shared__ char raw[];
    __half2* tile = (__half2*)raw;                     // 128*128 half2 = 65,536 B
    float2* tw = (float2*)(raw + 65536);
    init_tw1(tw, 256);
    const int tid = threadIdx.x, w2 = tid >> 5, lane = tid & 31;
    const int t = lane & 7, q = (lane >> 3) & 1, h = lane >> 4;
    const size_t base = (size_t)blockIdx.x * SLAB;
    float2 r[16];
    __syncthreads();
    #pragma unroll 1
    for (int it = 0; it < 4; ++it) {                   // x-dim, pattern A' (float2 gmem in)
        const int y = 2 * w2 + 32 * (it >> 1) + 16 * q + h + 64 * (it & 1);
        const float* p1 = v1 + base + y * VDIM + 2 * t;
        const float* p2 = v2 + base + y * VDIM + 2 * t;
        #pragma unroll
        for (int j = 0; j < 8; ++j) {
            const float2 a = *(const float2*)(p1 + 16 * j);
            const float2 b = *(const float2*)(p2 + 16 * j);
            r[2 * j]     = make_float2(a.x, b.x);
            r[2 * j + 1] = make_float2(a.y, b.y);
        }
        fftA2_fwd(r, t, tw);
        #pragma unroll
        for (int k = 0; k < 16; ++k)
            tile[sidxAC(y, 16 * (k >> 1) + 2 * t + (k & 1))] = pack_h2(r[k]);
    }
    __syncwarp();
    #pragma unroll 1
    for (int it = 0; it < 4; ++it) {                   // x-dim, pattern B'
        const int y = 2 * w2 + 32 * (it >> 1) + q + 16 * h + 64 * (it & 1);
        #pragma unroll
        for (int m = 0; m < 16; ++m) r[m] = unpack_h2(tile[sidxAC(y, 16 * t + m)]);
        fftB2_fwd(r);
        #pragma unroll
        for (int m = 0; m < 16; ++m) tile[sidxAC(y, 16 * t + m)] = pack_h2(r[m]);
    }
    __syncthreads();
    #pragma unroll 1
    for (int it = 0; it < 4; ++it) {                   // y-dim, pattern A'
        const int x = 2 * w2 + 32 * (it >> 1) + 16 * q + h + 64 * (it & 1);
        #pragma unroll
        for (int k = 0; k < 16; ++k)
            r[k] = unpack_h2(tile[sidxAC(16 * (k >> 1) + 2 * t + (k & 1), x)]);
        fftA2_fwd(r, t, tw);
        #pragma unroll
        for (int k = 0; k < 16; ++k)
            tile[sidxAC(16 * (k >> 1) + 2 * t + (k & 1), x)] = pack_h2(r[k]);
    }
    __syncthreads();
    #pragma unroll 1
    for (int it = 0; it < 4; ++it) {                   // y-dim, pattern B' (coalesced g_Z out)
        const int x = lane + 32 * (it >> 1) + 64 * (it & 1);
        #pragma unroll
        for (int m = 0; m < 16; ++m) r[m] = unpack_h2(tile[sidxAC(16 * w2 + m, x)]);
        fftB2_fwd(r);
        #pragma unroll
        for (int m = 0; m < 16; ++m)
            g_Z[base + (size_t)(16 * w2 + m) * VDIM + x] = pack_h2(r[m]);
    }
}

__device__ __forceinline__ float2 Hval(float2 Z, float2 Zn) {
    const float px = Z.x + Zn.x, py = Z.y - Zn.y;   // 2*F1
    const float qx = Z.x - Zn.x, qy = Z.y + Zn.y;   // 2i*F2
    return make_float2(0.25f * (px * qy - py * qx),
                       0.25f * (px * qx + py * qy));
}

// Pass B: z-FFT + pointwise + inverse z-FFT; fp32 tile, 256 thr, 2 CTAs/SM.
__global__ __launch_bounds__(256, 2) void passB() {
    extern __shared__ char raw[];
    float2* tile = (float2*)raw;                    // 64 lines x 128 (z)
    float2* tw = tile + 64 * 128; float2* tw4 = tw + 64; float2* tw8 = tw4 + 16;
    const int xt = blockIdx.x, jy = blockIdx.y, b = blockIdx.z;
    const int jy2 = bneg7(jy);
    const int xt2 = (xt < 2) ? xt : (5 - xt);
    if (jy2 < jy || (jy2 == jy && xt2 < xt)) return;
    const bool full = (jy2 == jy);
    init_tw3(tw, tw4, tw8, 256);
    const int tid = threadIdx.x;
    const int t = (tid >> 4) & 7;
    const int l0 = ((tid >> 7) << 4) | (tid & 15);
    const int l1 = l0 + 32;
    const size_t vb = (size_t)b * VOL;
    const size_t gb0 = vb + (size_t)jy  * VDIM + (32 * xt  + l0);
    const size_t gb1 = vb + (size_t)jy2 * VDIM + (32 * xt2 + l0);
    const float SCL = 1.0f / (float)VOL;
    float2 r[16];
    __syncthreads();
    #pragma unroll
    for (int j = 0; j < 16; ++j) r[j] = unpack_h2(g_Z[gb0 + (size_t)(t + 8 * j) * SLAB]);
    fftA_fwd(r, t, tw, tw4, tw8);
    #pragma unroll
    for (int j = 0; j < 16; ++j) tile[sidxB(l0, t + 8 * j)] = r[j];
    #pragma unroll
    for (int j = 0; j < 16; ++j) r[j] = unpack_h2(g_Z[gb1 + (size_t)(t + 8 * j) * SLAB]);
    fftA_fwd(r, t, tw, tw4, tw8);
    #pragma unroll
    for (int j = 0; j < 16; ++j) tile[sidxB(l1, t + 8 * j)] = r[j];
    __syncthreads();
    #pragma unroll
    for (int m = 0; m < 16; ++m) r[m] = tile[sidxB(l0, 16 * t + m)];
    fftB_fwd(r);
    #pragma unroll
    for (int m = 0; m < 16; ++m) tile[sidxB(l0, 16 * t + m)] = r[m];
    #pragma unroll
    for (int m = 0; m < 16; ++m) r[m] = tile[sidxB(l1, 16 * t + m)];
    fftB_fwd(r);
    #pragma unroll
    for (int m = 0; m < 16; ++m) tile[sidxB(l1, 16 * t + m)] = r[m];
    __syncthreads();
    #pragma unroll 1
    for (int i = tid; i < 32 * 128; i += 256) {
        const int jz = i & 127, row = i >> 7;
        const int jzn = bneg7(jz);
        if (jzn < jz) continue;
        const int pr = 32 + bneg7(32 * xt + row) - 32 * xt2;
        const float2 a1 = tile[sidxB(row, jz)], a2 = tile[sidxB(row, jzn)];
        const float2 b1 = tile[sidxB(pr, jz)],  b2 = tile[sidxB(pr, jzn)];
        tile[sidxB(row, jz)]  = Hval(a1, b2);
        tile[sidxB(pr, jz)]   = Hval(b1, a2);
        tile[sidxB(row, jzn)] = Hval(a2, b1);
        tile[sidxB(pr, jzn)]  = Hval(b2, a1);
    }
    __syncthreads();
    #pragma unroll
    for (int m = 0; m < 16; ++m) r[m] = tile[sidxB(l0, 16 * t + m)];
    fftB_inv(r);
    #pragma unroll
    for (int m = 0; m < 16; ++m) tile[sidxB(l0, 16 * t + m)] = r[m];
    if (full) {
        #pragma unroll
        for (int m = 0; m < 16; ++m) r[m] = tile[sidxB(l1, 16 * t + m)];
        fftB_inv(r);
        #pragma unroll
        for (int m = 0; m < 16; ++m) tile[sidxB(l1, 16 * t + m)] = r[m];
    }
    __syncthreads();
    #pragma unroll
    for (int j = 0; j < 16; ++j) r[j] = tile[sidxB(l0, t + 8 * j)];
    fftA_inv(r, t, tw, tw4, tw8);
    #pragma unroll
    for (int j = 0; j < 16; ++j)
        g_Z[gb0 + (size_t)(t + 8 * j) * SLAB] =
            pack_h2(make_float2(r[j].x * SCL, r[j].y * SCL));
    if (full) {
        #pragma unroll
        for (int j = 0; j < 16; ++j) r[j] = tile[sidxB(l1, t + 8 * j)];
        fftA_inv(r, t, tw, tw4, tw8);
        #pragma unroll
        for (int j = 0; j < 16; ++j)
            g_Z[gb1 + (size_t)(t + 8 * j) * SLAB] =
                pack_h2(make_float2(r[j].x * SCL, r[j].y * SCL));
    }
}

// Pass C: gather half-spectrum + mirror conj fill, inverse y then x FFTs, float2 out.
__global__ __launch_bounds__(256, 2) void passC(float* __restrict__ out) {
    extern __shared__ char raw[];
    __half2* tile = (__half2*)raw;
    float2* tw = (float2*)(raw + 65536);
    init_tw1(tw, 256);
    const int tid = threadIdx.x, w2 = tid >> 5, lane = tid & 31;
    const int t = lane & 7, q = (lane >> 3) & 1, h = lane >> 4;
    const size_t base = (size_t)blockIdx.x * SLAB;
    float2 r[16];
    __syncthreads();
    // gather copy-in: load kept rows (jy <= bneg7(jy)); mirror-fill conj rows.
    #pragma unroll 1
    for (int jy = w2; jy < 128; jy += 8) {
        const int jy2 = bneg7(jy);
        if (jy > jy2) continue;
        #pragma unroll
        for (int k = 0; k < 4; ++k) {
            const int xx = lane + 32 * k;
            __half2 v = g_Z[base + (size_t)jy * VDIM + xx];
            tile[sidxAC(jy, xx)] = v;
            if (jy2 != jy) {
                __half2 c = v; c.y = __hneg(c.y);
                tile[sidxAC(jy2, bneg7(xx))] = c;
            }
        }
    }
    __syncthreads();
    #pragma unroll 1
    for (int it = 0; it < 4; ++it) {                   // y-dim, pattern B' (from smem)
        const int x = lane + 32 * (it >> 1) + 64 * (it & 1);
        #pragma unroll
        for (int m = 0; m < 16; ++m) r[m] = unpack_h2(tile[sidxAC(16 * w2 + m, x)]);
        fftB2_inv(r);
        #pragma unroll
        for (int m = 0; m < 16; ++m) tile[sidxAC(16 * w2 + m, x)] = pack_h2(r[m]);
    }
    __syncthreads();
    #pragma unroll 1
    for (int it = 0; it < 4; ++it) {                   // y-dim, pattern A'
        const int x = 2 * w2 + 32 * (it >> 1) + 16 * q + h + 64 * (it & 1);
        #pragma unroll
        for (int k = 0; k < 16; ++k)
            r[k] = unpack_h2(tile[sidxAC(16 * (k >> 1) + 2 * t + (k & 1), x)]);
        fftA2_inv(r, t, tw);
        #pragma unroll
        for (int k = 0; k < 16; ++k)
            tile[sidxAC(16 * (k >> 1) + 2 * t + (k & 1), x)] = pack_h2(r[k]);
    }
    __syncthreads();
    #pragma unroll 1
    for (int it = 0; it < 4; ++it) {                   // x-dim, pattern B'
        const int y = 2 * w2 + 32 * (it >> 1) + q + 16 * h + 64 * (it & 1);
        #pragma unroll
        for (int m = 0; m < 16; ++m) r[m] = unpack_h2(tile[sidxAC(y, 16 * t + m)]);
        fftB2_inv(r);
        #pragma unroll
        for (int m = 0; m < 16; ++m) tile[sidxAC(y, 16 * t + m)] = pack_h2(r[m]);
    }
    __syncwarp();
    #pragma unroll 1
    for (int it = 0; it < 4; ++it) {                   // x-dim, pattern A' -> float2 out
        const int y = 2 * w2 + 32 * (it >> 1) + 16 * q + h + 64 * (it & 1);
        #pragma unroll
        for (int k = 0; k < 16; ++k)
            r[k] = unpack_h2(tile[sidxAC(y, 16 * (k >> 1) + 2 * t + (k & 1))]);
        fftA2_inv(r, t, tw);
        float* po = out + base + y * VDIM + 2 * t;
        #pragma unroll
        for (int j = 0; j < 8; ++j)
            *(float2*)(po + 16 * j) = make_float2(r[2 * j].x, r[2 * j + 1].x);
    }
}

extern "C" void kernel_launch(void* const* d_in, const int* in_sizes, int n_in,
                              void* d_out, int out_size) {
    const float* v1 = (const float*)d_in[0];
    const float* v2 = (const float*)d_in[1];
    float* out = (float*)d_out;
    const int smAC = 65536 + 64 * (int)sizeof(float2);                 // 66,048 B
    const int smB  = (64 * 128 + 64 + 16 + 8) * (int)sizeof(float2);   // 66,240 B
    cudaFuncSetAttribute(passA, cudaFuncAttributeMaxDynamicSharedMemorySize, smAC);
    cudaFuncSetAttribute(passC, cudaFuncAttributeMaxDynamicSharedMemorySize, smAC);
    cudaFuncSetAttribute(passB, cudaFuncAttributeMaxDynamicSharedMemorySize, smB);
    passA<<<NB * VDIM, 256, smAC>>>(v1, v2);
    passB<<<dim3(4, VDIM, NB), 256, smB>>>();
    passC<<<NB * VDIM, 256, smAC>>>(out);
}

// round 17
// speedup vs baseline: 1.1482x; 1.0638x over previous
#include <cuda_runtime.h>
#include <cuda_fp16.h>

#define VDIM 128
#define NB   8
#define SLAB 16384
#define VOL  2097152

// Scratch spectrum stored as half2, slab-major: idx = b*VOL + z*SLAB + y*128 + x.
__device__ __half2 g_Z[(size_t)NB * VOL];

__device__ __forceinline__ int brev7(int x) { return (int)(__brev((unsigned)x) >> 25); }
__device__ __forceinline__ int bneg7(int j) {
    int k = brev7(j); k = (VDIM - k) & 127; return brev7(k);
}

__device__ __forceinline__ __half2 pack_h2(float2 v) { return __floats2half2_rn(v.x, v.y); }
__device__ __forceinline__ float2 unpack_h2(__half2 h) { return __half22float2(h); }

// passA/C half2-tile swizzle: 32-bit/32-lane bank-bijective for all phases.
__device__ __forceinline__ int sidxAC(int y, int x) {
    int c = x ^ ((x >> 4) & 7) ^ ((x & 1) << 3)
              ^ (y & 7) ^ ((y >> 4) & 7) ^ ((y & 1) << 3) ^ (y & 8) ^ ((y & 1) << 4);
    return (y << 7) + c;
}
// passB fp32-tile swizzle (64-bit criterion, proven in earlier rounds).
__device__ __forceinline__ int sidxB(int l, int z) {
    int c = z ^ ((z >> 4) & 7) ^ (l & 15);
    return (l << 7) + c;
}

// Twiddle constants for specialized stages.
#define C8F 0.92387953251128674f
#define S8F 0.38268343236508978f
#define C4F 0.70710678118654752f

__device__ __forceinline__ float2 cmul(float2 a, float2 w) {
    return make_float2(a.x * w.x - a.y * w.y, a.x * w.y + a.y * w.x);
}
__device__ __forceinline__ float2 cmulc(float2 a, float2 w) {
    return make_float2(a.x * w.x + a.y * w.y, a.y * w.x - a.x * w.y);
}
__device__ __forceinline__ void bf_fwd(float2& ra, float2& rb, float2 w) {
    float2 a = ra, b = rb;
    ra = make_float2(a.x + b.x, a.y + b.y);
    rb = cmul(make_float2(a.x - b.x, a.y - b.y), w);
}
__device__ __forceinline__ void bf_inv(float2& ra, float2& rb, float2 w) {
    float2 a = ra, t = cmulc(rb, w);
    ra = make_float2(a.x + t.x, a.y + t.y);
    rb = make_float2(a.x - t.x, a.y - t.y);
}
__device__ __forceinline__ void bf_triv_fwd(float2& ra, float2& rb) {
    float2 a = ra, b = rb;
    ra = make_float2(a.x + b.x, a.y + b.y);
    rb = make_float2(a.x - b.x, a.y - b.y);
}
__device__ __forceinline__ void bf_fwd_c(float2& ra, float2& rb, float wx, float wy) {
    float2 a = ra, b = rb;
    ra = make_float2(a.x + b.x, a.y + b.y);
    float dx = a.x - b.x, dy = a.y - b.y;
    rb = make_float2(dx * wx - dy * wy, dx * wy + dy * wx);
}
__device__ __forceinline__ void bf_inv_c(float2& ra, float2& rb, float wx, float wy) {
    float2 a = ra;
    float tx = rb.x * wx + rb.y * wy, ty = rb.y * wx - rb.x * wy;
    ra = make_float2(a.x + tx, a.y + ty);
    rb = make_float2(a.x - tx, a.y - ty);
}
__device__ __forceinline__ void bf_fwd_mi(float2& ra, float2& rb) {
    float2 a = ra, b = rb;
    ra = make_float2(a.x + b.x, a.y + b.y);
    rb = make_float2(a.y - b.y, b.x - a.x);
}
__device__ __forceinline__ void bf_inv_mi(float2& ra, float2& rb) {
    float2 a = ra;
    float tx = -rb.y, ty = rb.x;
    ra = make_float2(a.x + tx, a.y + ty);
    rb = make_float2(a.x - tx, a.y - ty);
}

// ===== A'/B' split (all passes) =====
__device__ __forceinline__ void fftA2_fwd(float2 r[16], int t, const float2* tw) {
    #pragma unroll
    for (int k = 0; k < 8; ++k)
        bf_fwd(r[k], r[k + 8], tw[16 * (k >> 1) + 2 * t + (k & 1)]);
    #pragma unroll
    for (int g = 0; g < 8; ++g) { int k = ((g & ~3) << 1) | (g & 3);
        bf_fwd(r[k], r[k + 4], tw[32 * ((k >> 1) & 1) + 4 * t + 2 * (k & 1)]); }
    #pragma unroll
    for (int g = 0; g < 8; ++g) { int k = ((g & ~1) << 1) | (g & 1);
        bf_fwd(r[k], r[k + 2], tw[8 * t + 4 * (k & 1)]); }
}
__device__ __forceinline__ void fftA2_inv(float2 r[16], int t, const float2* tw) {
    #pragma unroll
    for (int g = 0; g < 8; ++g) { int k = ((g & ~1) << 1) | (g & 1);
        bf_inv(r[k], r[k + 2], tw[8 * t + 4 * (k & 1)]); }
    #pragma unroll
    for (int g = 0; g < 8; ++g) { int k = ((g & ~3) << 1) | (g & 3);
        bf_inv(r[k], r[k + 4], tw[32 * ((k >> 1) & 1) + 4 * t + 2 * (k & 1)]); }
    #pragma unroll
    for (int k = 0; k < 8; ++k)
        bf_inv(r[k], r[k + 8], tw[16 * (k >> 1) + 2 * t + (k & 1)]);
}
// B' stages (8,4,2,1) with compile-time twiddles.
__device__ __forceinline__ void fftB2_fwd(float2 r[16]) {
    bf_triv_fwd(r[0], r[8]);
    bf_fwd_c(r[1], r[9],  C8F, -S8F);
    bf_fwd_c(r[2], r[10], C4F, -C4F);
    bf_fwd_c(r[3], r[11], S8F, -C8F);
    bf_fwd_mi(r[4], r[12]);
    bf_fwd_c(r[5], r[13], -S8F, -C8F);
    bf_fwd_c(r[6], r[14], -C4F, -C4F);
    bf_fwd_c(r[7], r[15], -C8F, -S8F);
    bf_triv_fwd(r[0], r[4]);  bf_fwd_c(r[1], r[5],  C4F, -C4F);
    bf_fwd_mi(r[2], r[6]);    bf_fwd_c(r[3], r[7],  -C4F, -C4F);
    bf_triv_fwd(r[8], r[12]); bf_fwd_c(r[9], r[13], C4F, -C4F);
    bf_fwd_mi(r[10], r[14]);  bf_fwd_c(r[11], r[15], -C4F, -C4F);
    bf_triv_fwd(r[0], r[2]);   bf_fwd_mi(r[1], r[3]);
    bf_triv_fwd(r[4], r[6]);   bf_fwd_mi(r[5], r[7]);
    bf_triv_fwd(r[8], r[10]);  bf_fwd_mi(r[9], r[11]);
    bf_triv_fwd(r[12], r[14]); bf_fwd_mi(r[13], r[15]);
    #pragma unroll
    for (int g = 0; g < 8; ++g) bf_triv_fwd(r[2 * g], r[2 * g + 1]);
}
__device__ __forceinline__ void fftB2_inv(float2 r[16]) {
    #pragma unroll
    for (int g = 0; g < 8; ++g) bf_triv_fwd(r[2 * g], r[2 * g + 1]);
    bf_triv_fwd(r[0], r[2]);   bf_inv_mi(r[1], r[3]);
    bf_triv_fwd(r[4], r[6]);   bf_inv_mi(r[5], r[7]);
    bf_triv_fwd(r[8], r[10]);  bf_inv_mi(r[9], r[11]);
    bf_triv_fwd(r[12], r[14]); bf_inv_mi(r[13], r[15]);
    bf_triv_fwd(r[0], r[4]);  bf_inv_c(r[1], r[5],  C4F, -C4F);
    bf_inv_mi(r[2], r[6]);    bf_inv_c(r[3], r[7],  -C4F, -C4F);
    bf_triv_fwd(r[8], r[12]); bf_inv_c(r[9], r[13], C4F, -C4F);
    bf_inv_mi(r[10], r[14]);  bf_inv_c(r[11], r[15], -C4F, -C4F);
    bf_triv_fwd(r[0], r[8]);
    bf_inv_c(r[1], r[9],  C8F, -S8F);
    bf_inv_c(r[2], r[10], C4F, -C4F);
    bf_inv_c(r[3], r[11], S8F, -C8F);
    bf_inv_mi(r[4], r[12]);
    bf_inv_c(r[5], r[13], -S8F, -C8F);
    bf_inv_c(r[6], r[14], -C4F, -C4F);
    bf_inv_c(r[7], r[15], -C8F, -S8F);
}
__device__ __forceinline__ void init_tw1(float2* tw, int nthr) {
    for (int i = threadIdx.x; i < 64; i += nthr) {
        float sn, cs; sincospif(i * (1.0f / 64.0f), &sn, &cs);
        tw[i] = make_float2(cs, -sn);
    }
}

// Pass A: pack v1 + i*v2, forward FFT along x then y per (b,z) slab.
__global__ __launch_bounds__(256, 2) void passA(const float* __restrict__ v1,
                                                const float* __restrict__ v2) {
    extern __shared__ char raw[];
    __half2* tile = (__half2*)raw;                     // 128*128 half2 = 65,536 B
    float2* tw = (float2*)(raw + 65536);
    init_tw1(tw, 256);
    const int tid = threadIdx.x, w2 = tid >> 5, lane = tid & 31;
    const int t = lane & 7, q = (lane >> 3) & 1, h = lane >> 4;
    const size_t base = (size_t)blockIdx.x * SLAB;
    float2 r[16];
    __syncthreads();
    #pragma unroll 1
    for (int it = 0; it < 4; ++it) {                   // x-dim, pattern A' (float2 gmem in)
        const int y = 2 * w2 + 32 * (it >> 1) + 16 * q + h + 64 * (it & 1);
        const float* p1 = v1 + base + y * VDIM + 2 * t;
        const float* p2 = v2 + base + y * VDIM + 2 * t;
        #pragma unroll
        for (int j = 0; j < 8; ++j) {
            const float2 a = *(const float2*)(p1 + 16 * j);
            const float2 b = *(const float2*)(p2 + 16 * j);
            r[2 * j]     = make_float2(a.x, b.x);
            r[2 * j + 1] = make_float2(a.y, b.y);
        }
        fftA2_fwd(r, t, tw);
        #pragma unroll
        for (int k = 0; k < 16; ++k)
            tile[sidxAC(y, 16 * (k >> 1) + 2 * t + (k & 1))] = pack_h2(r[k]);
    }
    __syncwarp();
    #pragma unroll 1
    for (int it = 0; it < 4; ++it) {                   // x-dim, pattern B'
        const int y = 2 * w2 + 32 * (it >> 1) + q + 16 * h + 64 * (it & 1);
        #pragma unroll
        for (int m = 0; m < 16; ++m) r[m] = unpack_h2(tile[sidxAC(y, 16 * t + m)]);
        fftB2_fwd(r);
        #pragma unroll
        for (int m = 0; m < 16; ++m) tile[sidxAC(y, 16 * t + m)] = pack_h2(r[m]);
    }
    __syncthreads();
    #pragma unroll 1
    for (int it = 0; it < 4; ++it) {                   // y-dim, pattern A'
        const int x = 2 * w2 + 32 * (it >> 1) + 16 * q + h + 64 * (it & 1);
        #pragma unroll
        for (int k = 0; k < 16; ++k)
            r[k] = unpack_h2(tile[sidxAC(16 * (k >> 1) + 2 * t + (k & 1), x)]);
        fftA2_fwd(r, t, tw);
        #pragma unroll
        for (int k = 0; k < 16; ++k)
            tile[sidxAC(16 * (k >> 1) + 2 * t + (k & 1), x)] = pack_h2(r[k]);
    }
    __syncthreads();
    #pragma unroll 1
    for (int it = 0; it < 4; ++it) {                   // y-dim, pattern B' (coalesced g_Z out)
        const int x = lane + 32 * (it >> 1) + 64 * (it & 1);
        #pragma unroll
        for (int m = 0; m < 16; ++m) r[m] = unpack_h2(tile[sidxAC(16 * w2 + m, x)]);
        fftB2_fwd(r);
        #pragma unroll
        for (int m = 0; m < 16; ++m)
            g_Z[base + (size_t)(16 * w2 + m) * VDIM + x] = pack_h2(r[m]);
    }
}

__device__ __forceinline__ float2 Hval(float2 Z, float2 Zn) {
    const float px = Z.x + Zn.x, py = Z.y - Zn.y;   // 2*F1
    const float qx = Z.x - Zn.x, qy = Z.y + Zn.y;   // 2i*F2
    return make_float2(0.25f * (px * qy - py * qx),
                       0.25f * (px * qx + py * qy));
}

// Pass B: z-FFT + pointwise + inverse z-FFT; fp32 tile, 2 CTAs/SM.
// A'/B' split (specialized low stages) + divergence-free even-jz pointwise.
__global__ __launch_bounds__(256, 2) void passB() {
    extern __shared__ char raw[];
    float2* tile = (float2*)raw;                    // 64 lines x 128 (z)
    float2* tw = (float2*)(raw + 64 * 128 * sizeof(float2));
    const int xt = blockIdx.x, jy = blockIdx.y, b = blockIdx.z;
    const int jy2 = bneg7(jy);
    const int xt2 = (xt < 2) ? xt : (5 - xt);
    if (jy2 < jy || (jy2 == jy && xt2 < xt)) return;
    const bool full = (jy2 == jy);
    init_tw1(tw, 256);
    const int tid = threadIdx.x;
    const int t = (tid >> 4) & 7;
    const int l0 = ((tid >> 7) << 4) | (tid & 15);
    const int l1 = l0 + 32;
    const size_t vb = (size_t)b * VOL;
    const size_t gb0 = vb + (size_t)jy  * VDIM + (32 * xt  + l0);
    const size_t gb1 = vb + (size_t)jy2 * VDIM + (32 * xt2 + l0);
    const float SCL = 1.0f / (float)VOL;
    float2 r[16];
    __syncthreads();
    // forward z pattern A' (both slots)
    #pragma unroll
    for (int k = 0; k < 16; ++k) {
        const int zk = 16 * (k >> 1) + 2 * t + (k & 1);
        r[k] = unpack_h2(g_Z[gb0 + (size_t)zk * SLAB]);
    }
    fftA2_fwd(r, t, tw);
    #pragma unroll
    for (int k = 0; k < 16; ++k)
        tile[sidxB(l0, 16 * (k >> 1) + 2 * t + (k & 1))] = r[k];
    #pragma unroll
    for (int k = 0; k < 16; ++k) {
        const int zk = 16 * (k >> 1) + 2 * t + (k & 1);
        r[k] = unpack_h2(g_Z[gb1 + (size_t)zk * SLAB]);
    }
    fftA2_fwd(r, t, tw);
    #pragma unroll
    for (int k = 0; k < 16; ++k)
        tile[sidxB(l1, 16 * (k >> 1) + 2 * t + (k & 1))] = r[k];
    __syncthreads();
    // forward z pattern B' (both slots)
    #pragma unroll
    for (int m = 0; m < 16; ++m) r[m] = tile[sidxB(l0, 16 * t + m)];
    fftB2_fwd(r);
    #pragma unroll
    for (int m = 0; m < 16; ++m) tile[sidxB(l0, 16 * t + m)] = r[m];
    #pragma unroll
    for (int m = 0; m < 16; ++m) r[m] = tile[sidxB(l1, 16 * t + m)];
    fftB2_fwd(r);
    #pragma unroll
    for (int m = 0; m < 16; ++m) tile[sidxB(l1, 16 * t + m)] = r[m];
    __syncthreads();
    // pointwise: divergence-free. Kept jz set = {even jz} + {1}; quads partition the tile.
    #pragma unroll 1
    for (int i = tid; i < 32 * 64; i += 256) {
        const int jz = (i & 63) << 1, row = i >> 6;
        const int jzn = bneg7(jz);
        const int pr = 32 + bneg7(32 * xt + row) - 32 * xt2;
        const float2 a1 = tile[sidxB(row, jz)], a2 = tile[sidxB(row, jzn)];
        const float2 b1 = tile[sidxB(pr, jz)],  b2 = tile[sidxB(pr, jzn)];
        tile[sidxB(row, jz)]  = Hval(a1, b2);
        tile[sidxB(pr, jz)]   = Hval(b1, a2);
        tile[sidxB(row, jzn)] = Hval(a2, b1);
        tile[sidxB(pr, jzn)]  = Hval(b2, a1);
    }
    if (tid < 32) {                                   // jz = 1 (self-paired)
        const int row = tid;
        const int pr = 32 + bneg7(32 * xt + row) - 32 * xt2;
        const float2 a1 = tile[sidxB(row, 1)];
        const float2 b1 = tile[sidxB(pr, 1)];
        tile[sidxB(row, 1)] = Hval(a1, b1);
        tile[sidxB(pr, 1)]  = Hval(b1, a1);
    }
    __syncthreads();
    // inverse z pattern B' (slot0; slot1 only if self-paired)
    #pragma unroll
    for (int m = 0; m < 16; ++m) r[m] = tile[sidxB(l0, 16 * t + m)];
    fftB2_inv(r);
    #pragma unroll
    for (int m = 0; m < 16; ++m) tile[sidxB(l0, 16 * t + m)] = r[m];
    if (full) {
        #pragma unroll
        for (int m = 0; m < 16; ++m) r[m] = tile[sidxB(l1, 16 * t + m)];
        fftB2_inv(r);
        #pragma unroll
        for (int m = 0; m < 16; ++m) tile[sidxB(l1, 16 * t + m)] = r[m];
    }
    __syncthreads();
    // inverse z pattern A' + scaled fp16 store
    #pragma unroll
    for (int k = 0; k < 16; ++k)
        r[k] = tile[sidxB(l0, 16 * (k >> 1) + 2 * t + (k & 1))];
    fftA2_inv(r, t, tw);
    #pragma unroll
    for (int k = 0; k < 16; ++k) {
        const int zk = 16 * (k >> 1) + 2 * t + (k & 1);
        g_Z[gb0 + (size_t)zk * SLAB] =
            pack_h2(make_float2(r[k].x * SCL, r[k].y * SCL));
    }
    if (full) {
        #pragma unroll
        for (int k = 0; k < 16; ++k)
            r[k] = tile[sidxB(l1, 16 * (k >> 1) + 2 * t + (k & 1))];
        fftA2_inv(r, t, tw);
        #pragma unroll
        for (int k = 0; k < 16; ++k) {
            const int zk = 16 * (k >> 1) + 2 * t + (k & 1);
            g_Z[gb1 + (size_t)zk * SLAB] =
                pack_h2(make_float2(r[k].x * SCL, r[k].y * SCL));
        }
    }
}

// Pass C: gather half-spectrum + mirror conj fill, inverse y then x FFTs, float2 out.
__global__ __launch_bounds__(256, 2) void passC(float* __restrict__ out) {
    extern __shared__ char raw[];
    __half2* tile = (__half2*)raw;
    float2* tw = (float2*)(raw + 65536);
    init_tw1(tw, 256);
    const int tid = threadIdx.x, w2 = tid >> 5, lane = tid & 31;
    const int t = lane & 7, q = (lane >> 3) & 1, h = lane >> 4;
    const size_t base = (size_t)blockIdx.x * SLAB;
    float2 r[16];
    __syncthreads();
    // gather copy-in: load kept rows (jy <= bneg7(jy)); mirror-fill conj rows.
    #pragma unroll 1
    for (int jy = w2; jy < 128; jy += 8) {
        const int jy2 = bneg7(jy);
        if (jy > jy2) continue;
        #pragma unroll
        for (int k = 0; k < 4; ++k) {
            const int xx = lane + 32 * k;
            __half2 v = g_Z[base + (size_t)jy * VDIM + xx];
            tile[sidxAC(jy, xx)] = v;
            if (jy2 != jy) {
                __half2 c = v; c.y = __hneg(c.y);
                tile[sidxAC(jy2, bneg7(xx))] = c;
            }
        }
    }
    __syncthreads();
    #pragma unroll 1
    for (int it = 0; it < 4; ++it) {                   // y-dim, pattern B' (from smem)
        const int x = lane + 32 * (it >> 1) + 64 * (it & 1);
        #pragma unroll
        for (int m = 0; m < 16; ++m) r[m] = unpack_h2(tile[sidxAC(16 * w2 + m, x)]);
        fftB2_inv(r);
        #pragma unroll
        for (int m = 0; m < 16; ++m) tile[sidxAC(16 * w2 + m, x)] = pack_h2(r[m]);
    }
    __syncthreads();
    #pragma unroll 1
    for (int it = 0; it < 4; ++it) {                   // y-dim, pattern A'
        const int x = 2 * w2 + 32 * (it >> 1) + 16 * q + h + 64 * (it & 1);
        #pragma unroll
        for (int k = 0; k < 16; ++k)
            r[k] = unpack_h2(tile[sidxAC(16 * (k >> 1) + 2 * t + (k & 1), x)]);
        fftA2_inv(r, t, tw);
        #pragma unroll
        for (int k = 0; k < 16; ++k)
            tile[sidxAC(16 * (k >> 1) + 2 * t + (k & 1), x)] = pack_h2(r[k]);
    }
    __syncthreads();
    #pragma unroll 1
    for (int it = 0; it < 4; ++it) {                   // x-dim, pattern B'
        const int y = 2 * w2 + 32 * (it >> 1) + q + 16 * h + 64 * (it & 1);
        #pragma unroll
        for (int m = 0; m < 16; ++m) r[m] = unpack_h2(tile[sidxAC(y, 16 * t + m)]);
        fftB2_inv(r);
        #pragma unroll
        for (int m = 0; m < 16; ++m) tile[sidxAC(y, 16 * t + m)] = pack_h2(r[m]);
    }
    __syncwarp();
    #pragma unroll 1
    for (int it = 0; it < 4; ++it) {                   // x-dim, pattern A' -> float2 out
        const int y = 2 * w2 + 32 * (it >> 1) + 16 * q + h + 64 * (it & 1);
        #pragma unroll
        for (int k = 0; k < 16; ++k)
            r[k] = unpack_h2(tile[sidxAC(y, 16 * (k >> 1) + 2 * t + (k & 1))]);
        fftA2_inv(r, t, tw);
        float* po = out + base + y * VDIM + 2 * t;
        #pragma unroll
        for (int j = 0; j < 8; ++j)
            *(float2*)(po + 16 * j) = make_float2(r[2 * j].x, r[2 * j + 1].x);
    }
}

extern "C" void kernel_launch(void* const* d_in, const int* in_sizes, int n_in,
                              void* d_out, int out_size) {
    const float* v1 = (const float*)d_in[0];
    const float* v2 = (const float*)d_in[1];
    float* out = (float*)d_out;
    const int smAC = 65536 + 64 * (int)sizeof(float2);                 // 66,048 B
    const int smB  = 64 * 128 * (int)sizeof(float2) + 64 * (int)sizeof(float2); // 66,048 B
    cudaFuncSetAttribute(passA, cudaFuncAttributeMaxDynamicSharedMemorySize, smAC);
    cudaFuncSetAttribute(passC, cudaFuncAttributeMaxDynamicSharedMemorySize, smAC);
    cudaFuncSetAttribute(passB, cudaFuncAttributeMaxDynamicSharedMemorySize, smB);
    passA<<<NB * VDIM, 256, smAC>>>(v1, v2);
    passB<<<dim3(4, VDIM, NB), 256, smB>>>();
    passC<<<NB * VDIM, 256, smAC>>>(out);
}